// round 3
// baseline (speedup 1.0000x reference)
#include <cuda_runtime.h>

#define NN 50000
#define EE 1200000
#define GG 256
#define CC 10

// ---------------- scratch (device globals; no allocation allowed) ----------
__device__ __align__(16) float d_deg[NN];        // degree, then dinv in-place
__device__ __align__(16) float d_h[NN * 64];     // post-GEMM features
__device__ __align__(16) float d_agg[NN * 64];   // aggregated (pre-BN)
__device__ __align__(16) float d_act[NN * 64];   // post BN+ReLU activations
__device__ __align__(16) float d_bn[128];        // [0:64) sum, [64:128) sumsq
__device__ __align__(16) float d_pool[GG * 32];  // per-graph sums
__device__ __align__(16) float d_cnt[GG];        // per-graph node counts

// 16B vector reduction (no return) — 4x fewer atomic ops than scalar atomicAdd
__device__ __forceinline__ void red4(float* p, float a, float b, float c, float d) {
    asm volatile("red.global.add.v4.f32 [%0], {%1,%2,%3,%4};"
                 :: "l"(p), "f"(a), "f"(b), "f"(c), "f"(d) : "memory");
}

// ---------------- init ------------------------------------------------------
__global__ void zero_main() {
    int i = blockIdx.x * blockDim.x + threadIdx.x;
    if (i < NN) d_deg[i] = 0.f;
    if (i < GG * 32) d_pool[i] = 0.f;
    if (i < GG) d_cnt[i] = 0.f;
}

__global__ void zero_bn() {
    if (threadIdx.x < 128) d_bn[threadIdx.x] = 0.f;
}

__global__ void count_deg(const int* __restrict__ dst) {
    int i = blockIdx.x * blockDim.x + threadIdx.x;
    if (i < EE) atomicAdd(&d_deg[dst[i]], 1.f);
}

__global__ void make_dinv() {
    int i = blockIdx.x * blockDim.x + threadIdx.x;
    if (i < NN) d_deg[i] = rsqrtf(d_deg[i] + 1.f);  // deg includes self-loop
}

// ---------------- per-layer kernels -----------------------------------------
// h = in @ W ; agg = h * dinv^2 + b   (self-loop message + bias pre-added)
template <int FIN, int FOUT>
__global__ void gemm_init(const float* __restrict__ xin,
                          const float* __restrict__ W,
                          const float* __restrict__ b) {
    constexpr int NPB = 256 / FOUT;  // nodes per block
    __shared__ float Ws[FIN * FOUT];
    __shared__ float xs[NPB * FIN];
    __shared__ float bs[FOUT];
    const float* in = xin ? xin : d_act;

    int tid = threadIdx.x;
    for (int i = tid; i < FIN * FOUT; i += 256) Ws[i] = W[i];
    if (tid < FOUT) bs[tid] = b[tid];
    int nbase = blockIdx.x * NPB;
    for (int i = tid; i < NPB * FIN; i += 256) {
        int n = nbase + i / FIN;
        xs[i] = (n < NN) ? in[n * FIN + (i % FIN)] : 0.f;
    }
    __syncthreads();

    int ln = tid / FOUT, j = tid % FOUT;
    int n = nbase + ln;
    if (n >= NN) return;
    float acc = 0.f;
#pragma unroll
    for (int k = 0; k < FIN; k++) acc = fmaf(xs[ln * FIN + k], Ws[k * FOUT + j], acc);
    float di = d_deg[n];  // dinv
    d_h[n * FOUT + j] = acc;
    d_agg[n * FOUT + j] = fmaf(acc, di * di, bs[j]);
}

// agg[dst] += h[src] * dinv[src]*dinv[dst]   — one thread per (edge, 4-float chunk)
template <int FOUT>
__global__ void scatter(const int* __restrict__ src, const int* __restrict__ dst) {
    constexpr int CH = FOUT / 4;
    constexpr int SH = (FOUT == 64) ? 4 : 3;
    int idx = blockIdx.x * blockDim.x + threadIdx.x;
    if (idx >= EE * CH) return;
    int e = idx >> SH, c = idx & (CH - 1);
    int s = src[e], d = dst[e];
    float nrm = d_deg[s] * d_deg[d];
    const float4 v = *reinterpret_cast<const float4*>(&d_h[s * FOUT + c * 4]);
    red4(&d_agg[d * FOUT + c * 4], v.x * nrm, v.y * nrm, v.z * nrm, v.w * nrm);
}

// per-channel sum / sumsq over N rows (coalesced; few atomics per channel)
template <int FOUT>
__global__ void bn_stats() {
    int t = blockIdx.x * blockDim.x + threadIdx.x;  // 256x256 = 65536 threads
    int c = t % FOUT;
    int r = t / FOUT;
    const int step = (256 * 256) / FOUT;
    float s = 0.f, ss = 0.f;
    for (; r < NN; r += step) {
        float v = d_agg[r * FOUT + c];
        s += v;
        ss += v * v;
    }
    atomicAdd(&d_bn[c], s);
    atomicAdd(&d_bn[64 + c], ss);
}

// act = relu((agg - mu) * rsqrt(var+eps) * gamma + beta)
template <int FOUT>
__global__ void bn_apply(const float* __restrict__ g, const float* __restrict__ be) {
    int i = blockIdx.x * blockDim.x + threadIdx.x;
    if (i >= NN * FOUT) return;
    int c = i % FOUT;
    const float invn = 1.f / (float)NN;
    float mu = d_bn[c] * invn;
    float var = d_bn[64 + c] * invn - mu * mu;
    float rstd = rsqrtf(var + 1e-5f);
    float v = (d_agg[i] - mu) * rstd * g[c] + be[c];
    d_act[i] = fmaxf(v, 0.f);
}

// ---------------- pooling + classifier --------------------------------------
__global__ void pool_add(const int* __restrict__ batch) {
    int i = blockIdx.x * blockDim.x + threadIdx.x;
    if (i >= NN * 8) return;  // H2=32 -> 8 float4 chunks per node
    int n = i >> 3, c = i & 7;
    int g = batch[n];
    const float4 v = *reinterpret_cast<const float4*>(&d_act[n * 32 + c * 4]);
    red4(&d_pool[g * 32 + c * 4], v.x, v.y, v.z, v.w);
    if (c == 0) atomicAdd(&d_cnt[g], 1.f);
}

__global__ void classify(const float* __restrict__ Wl, const float* __restrict__ bl,
                         float* __restrict__ out) {
    int g = blockIdx.x * blockDim.x + threadIdx.x;
    if (g >= GG) return;
    float inv = 1.f / fmaxf(d_cnt[g], 1.f);
    float lo[CC];
#pragma unroll
    for (int c = 0; c < CC; c++) lo[c] = bl[c];
#pragma unroll
    for (int k = 0; k < 32; k++) {
        float p = d_pool[g * 32 + k] * inv;
#pragma unroll
        for (int c = 0; c < CC; c++) lo[c] = fmaf(p, Wl[k * CC + c], lo[c]);
    }
    float m = lo[0];
#pragma unroll
    for (int c = 1; c < CC; c++) m = fmaxf(m, lo[c]);
    float s = 0.f;
#pragma unroll
    for (int c = 0; c < CC; c++) { lo[c] = expf(lo[c] - m); s += lo[c]; }
    float is = 1.f / s;
#pragma unroll
    for (int c = 0; c < CC; c++) out[g * CC + c] = lo[c] * is;
}

// ---------------- launch -----------------------------------------------------
extern "C" void kernel_launch(void* const* d_in, const int* in_sizes, int n_in,
                              void* d_out, int out_size) {
    const float* x   = (const float*)d_in[0];
    const int* esrc  = (const int*)d_in[1];
    const int* edst  = (const int*)d_in[2];
    const int* batch = (const int*)d_in[3];
    const float* W1 = (const float*)d_in[4];   const float* b1 = (const float*)d_in[5];
    const float* W2 = (const float*)d_in[6];   const float* b2 = (const float*)d_in[7];
    const float* W4 = (const float*)d_in[8];   const float* b4 = (const float*)d_in[9];
    const float* W3 = (const float*)d_in[10];  const float* b3 = (const float*)d_in[11];
    const float* g1 = (const float*)d_in[12];  const float* be1 = (const float*)d_in[13];
    const float* g2 = (const float*)d_in[14];  const float* be2 = (const float*)d_in[15];
    const float* g4 = (const float*)d_in[16];  const float* be4 = (const float*)d_in[17];
    const float* g3 = (const float*)d_in[18];  const float* be3 = (const float*)d_in[19];
    const float* Wl = (const float*)d_in[20];  const float* bl = (const float*)d_in[21];
    float* out = (float*)d_out;

    zero_main<<<(NN + 255) / 256, 256>>>();
    count_deg<<<(EE + 255) / 256, 256>>>(edst);
    make_dinv<<<(NN + 255) / 256, 256>>>();

    // layer 1: x(64) -> 64
    gemm_init<64, 64><<<NN / 4, 256>>>(x, W1, b1);
    scatter<64><<<(EE * 16 + 255) / 256, 256>>>(esrc, edst);
    zero_bn<<<1, 128>>>();
    bn_stats<64><<<256, 256>>>();
    bn_apply<64><<<(NN * 64 + 255) / 256, 256>>>(g1, be1);

    // layer 2: 64 -> 64
    gemm_init<64, 64><<<NN / 4, 256>>>(nullptr, W2, b2);
    scatter<64><<<(EE * 16 + 255) / 256, 256>>>(esrc, edst);
    zero_bn<<<1, 128>>>();
    bn_stats<64><<<256, 256>>>();
    bn_apply<64><<<(NN * 64 + 255) / 256, 256>>>(g2, be2);

    // layer 3 (conv4): 64 -> 64
    gemm_init<64, 64><<<NN / 4, 256>>>(nullptr, W4, b4);
    scatter<64><<<(EE * 16 + 255) / 256, 256>>>(esrc, edst);
    zero_bn<<<1, 128>>>();
    bn_stats<64><<<256, 256>>>();
    bn_apply<64><<<(NN * 64 + 255) / 256, 256>>>(g4, be4);

    // layer 4 (conv3): 64 -> 32
    gemm_init<64, 32><<<NN / 8, 256>>>(nullptr, W3, b3);
    scatter<32><<<(EE * 8 + 255) / 256, 256>>>(esrc, edst);
    zero_bn<<<1, 128>>>();
    bn_stats<32><<<256, 256>>>();
    bn_apply<32><<<(NN * 32 + 255) / 256, 256>>>(g3, be3);

    // pool + classifier
    pool_add<<<(NN * 8 + 255) / 256, 256>>>(batch);
    classify<<<1, 256>>>(Wl, bl, out);
}

// round 4
// speedup vs baseline: 1.6875x; 1.6875x over previous
#include <cuda_runtime.h>

#define NN 50000
#define EE 1200000
#define GG 256
#define CC 10
#define NB 196   // scan blocks: ceil(NN/256)

// ---------------- scratch (device globals; no allocation allowed) ----------
__device__ __align__(16) float d_deg[NN];        // dinv
__device__ __align__(16) int   d_cnts[NN];       // in-degree (int)
__device__ __align__(16) int   d_rowptr[NN + 1];
__device__ __align__(16) int   d_cur[NN];        // fill cursors
__device__ __align__(16) int   d_bsum[NB];
__device__ __align__(16) int   d_boff[NB];
__device__ __align__(16) int2  d_csr[EE];        // {src, bitcast(dinv[src])}
__device__ __align__(16) float d_h[NN * 64];     // post-GEMM features
__device__ __align__(16) float d_agg[NN * 64];   // aggregated (pre-BN)
__device__ __align__(16) float d_act[NN * 64];   // post BN+ReLU
__device__ __align__(16) float d_bn[128];        // [0:64) sum, [64:128) sumsq
__device__ __align__(16) float d_pool[GG * 32];
__device__ __align__(16) float d_cnt[GG];

__device__ __forceinline__ void red4(float* p, float a, float b, float c, float d) {
    asm volatile("red.global.add.v4.f32 [%0], {%1,%2,%3,%4};"
                 :: "l"(p), "f"(a), "f"(b), "f"(c), "f"(d) : "memory");
}

// ---------------- setup ------------------------------------------------------
__global__ void zero_main() {
    int i = blockIdx.x * blockDim.x + threadIdx.x;
    if (i < NN) d_cnts[i] = 0;
    if (i < GG * 32) d_pool[i] = 0.f;
    if (i < GG) d_cnt[i] = 0.f;
}

__global__ void count_deg(const int* __restrict__ dst) {
    int i = blockIdx.x * blockDim.x + threadIdx.x;
    if (i < EE) atomicAdd(&d_cnts[dst[i]], 1);
}

__global__ void make_dinv() {
    int i = blockIdx.x * blockDim.x + threadIdx.x;
    if (i < NN) d_deg[i] = rsqrtf((float)d_cnts[i] + 1.f);
}

// three-kernel exclusive scan of d_cnts -> d_rowptr (+ cursor copy)
__global__ void scan_bsum() {
    int i = blockIdx.x * 256 + threadIdx.x;
    int v = (i < NN) ? d_cnts[i] : 0;
#pragma unroll
    for (int o = 16; o > 0; o >>= 1) v += __shfl_down_sync(0xffffffffu, v, o);
    __shared__ int sh[8];
    if ((threadIdx.x & 31) == 0) sh[threadIdx.x >> 5] = v;
    __syncthreads();
    if (threadIdx.x == 0) {
        int s = 0;
#pragma unroll
        for (int w = 0; w < 8; w++) s += sh[w];
        d_bsum[blockIdx.x] = s;
    }
}

__global__ void scan_tops() {
    if (threadIdx.x == 0) {
        int acc = 0;
        for (int b = 0; b < NB; b++) { d_boff[b] = acc; acc += d_bsum[b]; }
        d_rowptr[NN] = acc;
    }
}

__global__ void scan_final() {
    __shared__ int sh[256];
    int i = blockIdx.x * 256 + threadIdx.x;
    int v = (i < NN) ? d_cnts[i] : 0;
    sh[threadIdx.x] = v;
    __syncthreads();
#pragma unroll
    for (int o = 1; o < 256; o <<= 1) {
        int t = (threadIdx.x >= o) ? sh[threadIdx.x - o] : 0;
        __syncthreads();
        sh[threadIdx.x] += t;
        __syncthreads();
    }
    if (i < NN) {
        int excl = sh[threadIdx.x] - v + d_boff[blockIdx.x];
        d_rowptr[i] = excl;
        d_cur[i] = excl;
    }
}

__global__ void fill_csr(const int* __restrict__ src, const int* __restrict__ dst) {
    int e = blockIdx.x * blockDim.x + threadIdx.x;
    if (e >= EE) return;
    int s = src[e], d = dst[e];
    int pos = atomicAdd(&d_cur[d], 1);
    d_csr[pos] = make_int2(s, __float_as_int(d_deg[s]));
}

// ---------------- register-tiled GEMM: h = in @ W ---------------------------
// 256 threads; each computes a 4-node x 4-col register tile.
template <int FOUT>
__global__ void gemm_k(const float* __restrict__ xin, const float* __restrict__ W) {
    constexpr int CG = FOUT / 4;      // col groups   (16 or 8)
    constexpr int NG = 256 / CG;      // node groups  (16 or 32)
    constexpr int NODES = NG * 4;     // 64 or 128 nodes per block
    __shared__ float Ws[64 * FOUT];
    __shared__ float xs[NODES * 65];  // +1 float pad per row

    const float* in = xin ? xin : d_act;
    int tid = threadIdx.x;
    for (int i = tid; i < 64 * FOUT; i += 256) Ws[i] = W[i];
    int nbase = blockIdx.x * NODES;
    for (int i = tid; i < NODES * 64; i += 256) {
        int n = i >> 6, k = i & 63;
        xs[n * 65 + k] = (nbase + n < NN) ? in[(nbase + n) * 64 + k] : 0.f;
    }
    __syncthreads();

    int ng = tid & (NG - 1);
    int cg = tid / NG;
    float4 acc[4];
#pragma unroll
    for (int r = 0; r < 4; r++) acc[r] = make_float4(0.f, 0.f, 0.f, 0.f);

#pragma unroll
    for (int k = 0; k < 64; k++) {
        float4 w = *reinterpret_cast<const float4*>(&Ws[k * FOUT + cg * 4]);
#pragma unroll
        for (int r = 0; r < 4; r++) {
            float xv = xs[(ng + r * NG) * 65 + k];
            acc[r].x = fmaf(xv, w.x, acc[r].x);
            acc[r].y = fmaf(xv, w.y, acc[r].y);
            acc[r].z = fmaf(xv, w.z, acc[r].z);
            acc[r].w = fmaf(xv, w.w, acc[r].w);
        }
    }
#pragma unroll
    for (int r = 0; r < 4; r++) {
        int n = nbase + ng + r * NG;
        if (n < NN) *reinterpret_cast<float4*>(&d_h[n * FOUT + cg * 4]) = acc[r];
    }
}

// ---------------- CSR gather: one warp per dst node --------------------------
// agg[d] = dinv[d]*( sum_e dinv[s] h[s] + dinv[d] h[d] ) + b
template <int F>
__global__ void gather_k(const float* __restrict__ bias) {
    if (blockIdx.x == 0 && threadIdx.x < 128) d_bn[threadIdx.x] = 0.f;  // fused zero_bn
    int d = (blockIdx.x * blockDim.x + threadIdx.x) >> 5;
    int lane = threadIdx.x & 31;
    if (d >= NN) return;
    int e = d_rowptr[d], end = d_rowptr[d + 1];

    if (F == 64) {
        const float2* hp = (const float2*)d_h;
        float ax = 0.f, ay = 0.f;
        for (; e + 2 <= end; e += 2) {
            int2 p0 = d_csr[e];
            int2 p1 = d_csr[e + 1];
            float2 h0 = hp[p0.x * 32 + lane];
            float2 h1 = hp[p1.x * 32 + lane];
            float w0 = __int_as_float(p0.y), w1 = __int_as_float(p1.y);
            ax = fmaf(w0, h0.x, fmaf(w1, h1.x, ax));
            ay = fmaf(w0, h0.y, fmaf(w1, h1.y, ay));
        }
        if (e < end) {
            int2 p = d_csr[e];
            float2 hv = hp[p.x * 32 + lane];
            float w = __int_as_float(p.y);
            ax = fmaf(w, hv.x, ax);
            ay = fmaf(w, hv.y, ay);
        }
        float dd = d_deg[d];
        float2 hd = hp[d * 32 + lane];
        float2 o;
        o.x = fmaf(fmaf(dd, hd.x, ax), dd, bias[2 * lane]);
        o.y = fmaf(fmaf(dd, hd.y, ay), dd, bias[2 * lane + 1]);
        *reinterpret_cast<float2*>(&d_agg[d * 64 + lane * 2]) = o;
    } else {
        float a = 0.f;
        for (; e + 2 <= end; e += 2) {
            int2 p0 = d_csr[e];
            int2 p1 = d_csr[e + 1];
            float h0 = d_h[p0.x * 32 + lane];
            float h1 = d_h[p1.x * 32 + lane];
            a = fmaf(__int_as_float(p0.y), h0, fmaf(__int_as_float(p1.y), h1, a));
        }
        if (e < end) {
            int2 p = d_csr[e];
            a = fmaf(__int_as_float(p.y), d_h[p.x * 32 + lane], a);
        }
        float dd = d_deg[d];
        float hd = d_h[d * 32 + lane];
        d_agg[d * 32 + lane] = fmaf(fmaf(dd, hd, a), dd, bias[lane]);
    }
}

// ---------------- BN ---------------------------------------------------------
template <int FOUT>
__global__ void bn_stats() {
    int t = blockIdx.x * blockDim.x + threadIdx.x;  // 65536 threads
    int c = t % FOUT;
    int r = t / FOUT;
    const int step = (256 * 256) / FOUT;
    float s = 0.f, ss = 0.f;
    for (; r < NN; r += step) {
        float v = d_agg[r * FOUT + c];
        s += v;
        ss = fmaf(v, v, ss);
    }
    atomicAdd(&d_bn[c], s);
    atomicAdd(&d_bn[64 + c], ss);
}

template <int FOUT>
__global__ void bn_apply(const float* __restrict__ g, const float* __restrict__ be) {
    int i = blockIdx.x * blockDim.x + threadIdx.x;
    if (i >= NN * FOUT) return;
    int c = i % FOUT;
    const float invn = 1.f / (float)NN;
    float mu = d_bn[c] * invn;
    float var = d_bn[64 + c] * invn - mu * mu;
    float rstd = rsqrtf(var + 1e-5f);
    float v = (d_agg[i] - mu) * rstd * g[c] + be[c];
    d_act[i] = fmaxf(v, 0.f);
}

// ---------------- pooling + classifier --------------------------------------
__global__ void pool_add(const int* __restrict__ batch) {
    int i = blockIdx.x * blockDim.x + threadIdx.x;
    if (i >= NN * 8) return;
    int n = i >> 3, c = i & 7;
    int g = batch[n];
    const float4 v = *reinterpret_cast<const float4*>(&d_act[n * 32 + c * 4]);
    red4(&d_pool[g * 32 + c * 4], v.x, v.y, v.z, v.w);
    if (c == 0) atomicAdd(&d_cnt[g], 1.f);
}

__global__ void classify(const float* __restrict__ Wl, const float* __restrict__ bl,
                         float* __restrict__ out) {
    int g = blockIdx.x * blockDim.x + threadIdx.x;
    if (g >= GG) return;
    float inv = 1.f / fmaxf(d_cnt[g], 1.f);
    float lo[CC];
#pragma unroll
    for (int c = 0; c < CC; c++) lo[c] = bl[c];
#pragma unroll
    for (int k = 0; k < 32; k++) {
        float p = d_pool[g * 32 + k] * inv;
#pragma unroll
        for (int c = 0; c < CC; c++) lo[c] = fmaf(p, Wl[k * CC + c], lo[c]);
    }
    float m = lo[0];
#pragma unroll
    for (int c = 1; c < CC; c++) m = fmaxf(m, lo[c]);
    float s = 0.f;
#pragma unroll
    for (int c = 0; c < CC; c++) { lo[c] = expf(lo[c] - m); s += lo[c]; }
    float is = 1.f / s;
#pragma unroll
    for (int c = 0; c < CC; c++) out[g * CC + c] = lo[c] * is;
}

// ---------------- launch -----------------------------------------------------
extern "C" void kernel_launch(void* const* d_in, const int* in_sizes, int n_in,
                              void* d_out, int out_size) {
    const float* x   = (const float*)d_in[0];
    const int* esrc  = (const int*)d_in[1];
    const int* edst  = (const int*)d_in[2];
    const int* batch = (const int*)d_in[3];
    const float* W1 = (const float*)d_in[4];   const float* b1 = (const float*)d_in[5];
    const float* W2 = (const float*)d_in[6];   const float* b2 = (const float*)d_in[7];
    const float* W4 = (const float*)d_in[8];   const float* b4 = (const float*)d_in[9];
    const float* W3 = (const float*)d_in[10];  const float* b3 = (const float*)d_in[11];
    const float* g1 = (const float*)d_in[12];  const float* be1 = (const float*)d_in[13];
    const float* g2 = (const float*)d_in[14];  const float* be2 = (const float*)d_in[15];
    const float* g4 = (const float*)d_in[16];  const float* be4 = (const float*)d_in[17];
    const float* g3 = (const float*)d_in[18];  const float* be3 = (const float*)d_in[19];
    const float* Wl = (const float*)d_in[20];  const float* bl = (const float*)d_in[21];
    float* out = (float*)d_out;

    // setup: degrees + CSR by dst
    zero_main<<<(NN + 255) / 256, 256>>>();
    count_deg<<<(EE + 255) / 256, 256>>>(edst);
    make_dinv<<<(NN + 255) / 256, 256>>>();
    scan_bsum<<<NB, 256>>>();
    scan_tops<<<1, 32>>>();
    scan_final<<<NB, 256>>>();
    fill_csr<<<(EE + 255) / 256, 256>>>(esrc, edst);

    // layer 1: x(64) -> 64
    gemm_k<64><<<(NN + 63) / 64, 256>>>(x, W1);
    gather_k<64><<<(NN * 32 + 255) / 256, 256>>>(b1);
    bn_stats<64><<<256, 256>>>();
    bn_apply<64><<<(NN * 64 + 255) / 256, 256>>>(g1, be1);

    // layer 2: 64 -> 64
    gemm_k<64><<<(NN + 63) / 64, 256>>>(nullptr, W2);
    gather_k<64><<<(NN * 32 + 255) / 256, 256>>>(b2);
    bn_stats<64><<<256, 256>>>();
    bn_apply<64><<<(NN * 64 + 255) / 256, 256>>>(g2, be2);

    // layer 3 (conv4): 64 -> 64
    gemm_k<64><<<(NN + 63) / 64, 256>>>(nullptr, W4);
    gather_k<64><<<(NN * 32 + 255) / 256, 256>>>(b4);
    bn_stats<64><<<256, 256>>>();
    bn_apply<64><<<(NN * 64 + 255) / 256, 256>>>(g4, be4);

    // layer 4 (conv3): 64 -> 32
    gemm_k<32><<<(NN + 127) / 128, 256>>>(nullptr, W3);
    gather_k<32><<<(NN * 32 + 255) / 256, 256>>>(b3);
    bn_stats<32><<<256, 256>>>();
    bn_apply<32><<<(NN * 32 + 255) / 256, 256>>>(g3, be3);

    // pool + classifier
    pool_add<<<(NN * 8 + 255) / 256, 256>>>(batch);
    classify<<<1, 256>>>(Wl, bl, out);
}

// round 6
// speedup vs baseline: 1.6987x; 1.0067x over previous
#include <cuda_runtime.h>

#define NN 50000
#define EE 1200000
#define GG 256
#define CC 10
#define NB 196   // scan blocks: ceil(NN/256)

// ---------------- scratch (device globals; no allocation allowed) ----------
__device__ __align__(16) float d_deg[NN];        // dinv
__device__ __align__(16) int   d_cnts[NN];       // in-degree (int)
__device__ __align__(16) int   d_rowptr[NN + 1];
__device__ __align__(16) int   d_cur[NN];        // fill cursors
__device__ __align__(16) int   d_bsum[NB];
__device__ __align__(16) int   d_boff[NB];
__device__ __align__(16) int2  d_csr[EE];        // {src, bitcast(dinv[src])}
__device__ __align__(16) float d_h[NN * 64];     // post-GEMM features
__device__ __align__(16) float d_agg[NN * 64];   // aggregated (pre-BN)
__device__ __align__(16) float d_act[NN * 64];   // post BN+ReLU
__device__ __align__(16) float d_bn[128];        // [0:64) sum, [64:128) sumsq
__device__ __align__(16) float d_pool[GG * 32];
__device__ __align__(16) float d_cnt[GG];

__device__ __forceinline__ void red4(float* p, float a, float b, float c, float d) {
    asm volatile("red.global.add.v4.f32 [%0], {%1,%2,%3,%4};"
                 :: "l"(p), "f"(a), "f"(b), "f"(c), "f"(d) : "memory");
}

// ---------------- setup ------------------------------------------------------
__global__ void zero_main() {
    int i = blockIdx.x * blockDim.x + threadIdx.x;
    if (i < NN) d_cnts[i] = 0;
    if (i < GG * 32) d_pool[i] = 0.f;
    if (i < GG) d_cnt[i] = 0.f;
}

__global__ void count_deg(const int* __restrict__ dst) {
    int i = blockIdx.x * blockDim.x + threadIdx.x;
    if (i < EE) atomicAdd(&d_cnts[dst[i]], 1);
}

__global__ void make_dinv() {
    int i = blockIdx.x * blockDim.x + threadIdx.x;
    if (i < NN) d_deg[i] = rsqrtf((float)d_cnts[i] + 1.f);
}

// three-kernel exclusive scan of d_cnts -> d_rowptr (+ cursor copy)
__global__ void scan_bsum() {
    int i = blockIdx.x * 256 + threadIdx.x;
    int v = (i < NN) ? d_cnts[i] : 0;
#pragma unroll
    for (int o = 16; o > 0; o >>= 1) v += __shfl_down_sync(0xffffffffu, v, o);
    __shared__ int sh[8];
    if ((threadIdx.x & 31) == 0) sh[threadIdx.x >> 5] = v;
    __syncthreads();
    if (threadIdx.x == 0) {
        int s = 0;
#pragma unroll
        for (int w = 0; w < 8; w++) s += sh[w];
        d_bsum[blockIdx.x] = s;
    }
}

__global__ void scan_tops() {
    if (threadIdx.x == 0) {
        int acc = 0;
        for (int b = 0; b < NB; b++) { d_boff[b] = acc; acc += d_bsum[b]; }
        d_rowptr[NN] = acc;
    }
}

__global__ void scan_final() {
    __shared__ int sh[256];
    int i = blockIdx.x * 256 + threadIdx.x;
    int v = (i < NN) ? d_cnts[i] : 0;
    sh[threadIdx.x] = v;
    __syncthreads();
#pragma unroll
    for (int o = 1; o < 256; o <<= 1) {
        int t = (threadIdx.x >= o) ? sh[threadIdx.x - o] : 0;
        __syncthreads();
        sh[threadIdx.x] += t;
        __syncthreads();
    }
    if (i < NN) {
        int excl = sh[threadIdx.x] - v + d_boff[blockIdx.x];
        d_rowptr[i] = excl;
        d_cur[i] = excl;
    }
}

__global__ void fill_csr(const int* __restrict__ src, const int* __restrict__ dst) {
    int e = blockIdx.x * blockDim.x + threadIdx.x;
    if (e >= EE) return;
    int s = src[e], d = dst[e];
    int pos = atomicAdd(&d_cur[d], 1);
    d_csr[pos] = make_int2(s, __float_as_int(d_deg[s]));
}

// ---------------- register-tiled GEMM: h = in @ W ---------------------------
// 256 threads; each computes a 4-node x 4-col register tile.
template <int FOUT>
__global__ void gemm_k(const float* __restrict__ xin, const float* __restrict__ W) {
    constexpr int CG = FOUT / 4;      // col groups   (16 or 8)
    constexpr int NG = 256 / CG;      // node groups  (16 or 32)
    constexpr int NODES = NG * 4;     // 64 or 128 nodes per block
    __shared__ float Ws[64 * FOUT];
    __shared__ float xs[NODES * 65];  // +1 float pad per row

    const float* in = xin ? xin : d_act;
    int tid = threadIdx.x;
    for (int i = tid; i < 64 * FOUT; i += 256) Ws[i] = W[i];
    int nbase = blockIdx.x * NODES;
    for (int i = tid; i < NODES * 64; i += 256) {
        int n = i >> 6, k = i & 63;
        xs[n * 65 + k] = (nbase + n < NN) ? in[(nbase + n) * 64 + k] : 0.f;
    }
    __syncthreads();

    int ng = tid & (NG - 1);
    int cg = tid / NG;
    float4 acc[4];
#pragma unroll
    for (int r = 0; r < 4; r++) acc[r] = make_float4(0.f, 0.f, 0.f, 0.f);

#pragma unroll
    for (int k = 0; k < 64; k++) {
        float4 w = *reinterpret_cast<const float4*>(&Ws[k * FOUT + cg * 4]);
#pragma unroll
        for (int r = 0; r < 4; r++) {
            float xv = xs[(ng + r * NG) * 65 + k];
            acc[r].x = fmaf(xv, w.x, acc[r].x);
            acc[r].y = fmaf(xv, w.y, acc[r].y);
            acc[r].z = fmaf(xv, w.z, acc[r].z);
            acc[r].w = fmaf(xv, w.w, acc[r].w);
        }
    }
#pragma unroll
    for (int r = 0; r < 4; r++) {
        int n = nbase + ng + r * NG;
        if (n < NN) *reinterpret_cast<float4*>(&d_h[n * FOUT + cg * 4]) = acc[r];
    }
}

// ---------------- CSR gather: one warp per dst node --------------------------
// agg[d] = dinv[d]*( sum_e dinv[s] h[s] + dinv[d] h[d] ) + b
template <int F>
__global__ void gather_k(const float* __restrict__ bias) {
    if (blockIdx.x == 0 && threadIdx.x < 128) d_bn[threadIdx.x] = 0.f;  // fused zero_bn
    int d = (blockIdx.x * blockDim.x + threadIdx.x) >> 5;
    int lane = threadIdx.x & 31;
    if (d >= NN) return;
    int e = d_rowptr[d], end = d_rowptr[d + 1];

    if (F == 64) {
        const float2* hp = (const float2*)d_h;
        float ax = 0.f, ay = 0.f;
        for (; e + 2 <= end; e += 2) {
            int2 p0 = d_csr[e];
            int2 p1 = d_csr[e + 1];
            float2 h0 = hp[p0.x * 32 + lane];
            float2 h1 = hp[p1.x * 32 + lane];
            float w0 = __int_as_float(p0.y), w1 = __int_as_float(p1.y);
            ax = fmaf(w0, h0.x, fmaf(w1, h1.x, ax));
            ay = fmaf(w0, h0.y, fmaf(w1, h1.y, ay));
        }
        if (e < end) {
            int2 p = d_csr[e];
            float2 hv = hp[p.x * 32 + lane];
            float w = __int_as_float(p.y);
            ax = fmaf(w, hv.x, ax);
            ay = fmaf(w, hv.y, ay);
        }
        float dd = d_deg[d];
        float2 hd = hp[d * 32 + lane];
        float2 o;
        o.x = fmaf(fmaf(dd, hd.x, ax), dd, bias[2 * lane]);
        o.y = fmaf(fmaf(dd, hd.y, ay), dd, bias[2 * lane + 1]);
        *reinterpret_cast<float2*>(&d_agg[d * 64 + lane * 2]) = o;
    } else {
        float a = 0.f;
        for (; e + 2 <= end; e += 2) {
            int2 p0 = d_csr[e];
            int2 p1 = d_csr[e + 1];
            float h0 = d_h[p0.x * 32 + lane];
            float h1 = d_h[p1.x * 32 + lane];
            a = fmaf(__int_as_float(p0.y), h0, fmaf(__int_as_float(p1.y), h1, a));
        }
        if (e < end) {
            int2 p = d_csr[e];
            a = fmaf(__int_as_float(p.y), d_h[p.x * 32 + lane], a);
        }
        float dd = d_deg[d];
        float hd = d_h[d * 32 + lane];
        d_agg[d * 32 + lane] = fmaf(fmaf(dd, hd, a), dd, bias[lane]);
    }
}

// ---------------- BN ---------------------------------------------------------
template <int FOUT>
__global__ void bn_stats() {
    int t = blockIdx.x * blockDim.x + threadIdx.x;  // 65536 threads
    int c = t % FOUT;
    int r = t / FOUT;
    const int step = (256 * 256) / FOUT;
    float s = 0.f, ss = 0.f;
    for (; r < NN; r += step) {
        float v = d_agg[r * FOUT + c];
        s += v;
        ss = fmaf(v, v, ss);
    }
    atomicAdd(&d_bn[c], s);
    atomicAdd(&d_bn[64 + c], ss);
}

template <int FOUT>
__global__ void bn_apply(const float* __restrict__ g, const float* __restrict__ be) {
    int i = blockIdx.x * blockDim.x + threadIdx.x;
    if (i >= NN * FOUT) return;
    int c = i % FOUT;
    const float invn = 1.f / (float)NN;
    float mu = d_bn[c] * invn;
    float var = d_bn[64 + c] * invn - mu * mu;
    float rstd = rsqrtf(var + 1e-5f);
    float v = (d_agg[i] - mu) * rstd * g[c] + be[c];
    d_act[i] = fmaxf(v, 0.f);
}

// ---------------- pooling + classifier --------------------------------------
__global__ void pool_add(const int* __restrict__ batch) {
    int i = blockIdx.x * blockDim.x + threadIdx.x;
    if (i >= NN * 8) return;
    int n = i >> 3, c = i & 7;
    int g = batch[n];
    const float4 v = *reinterpret_cast<const float4*>(&d_act[n * 32 + c * 4]);
    red4(&d_pool[g * 32 + c * 4], v.x, v.y, v.z, v.w);
    if (c == 0) atomicAdd(&d_cnt[g], 1.f);
}

__global__ void classify(const float* __restrict__ Wl, const float* __restrict__ bl,
                         float* __restrict__ out) {
    int g = blockIdx.x * blockDim.x + threadIdx.x;
    if (g >= GG) return;
    float inv = 1.f / fmaxf(d_cnt[g], 1.f);
    float lo[CC];
#pragma unroll
    for (int c = 0; c < CC; c++) lo[c] = bl[c];
#pragma unroll
    for (int k = 0; k < 32; k++) {
        float p = d_pool[g * 32 + k] * inv;
#pragma unroll
        for (int c = 0; c < CC; c++) lo[c] = fmaf(p, Wl[k * CC + c], lo[c]);
    }
    float m = lo[0];
#pragma unroll
    for (int c = 1; c < CC; c++) m = fmaxf(m, lo[c]);
    float s = 0.f;
#pragma unroll
    for (int c = 0; c < CC; c++) { lo[c] = expf(lo[c] - m); s += lo[c]; }
    float is = 1.f / s;
#pragma unroll
    for (int c = 0; c < CC; c++) out[g * CC + c] = lo[c] * is;
}

// ---------------- launch -----------------------------------------------------
extern "C" void kernel_launch(void* const* d_in, const int* in_sizes, int n_in,
                              void* d_out, int out_size) {
    const float* x   = (const float*)d_in[0];
    const int* esrc  = (const int*)d_in[1];
    const int* edst  = (const int*)d_in[2];
    const int* batch = (const int*)d_in[3];
    const float* W1 = (const float*)d_in[4];   const float* b1 = (const float*)d_in[5];
    const float* W2 = (const float*)d_in[6];   const float* b2 = (const float*)d_in[7];
    const float* W4 = (const float*)d_in[8];   const float* b4 = (const float*)d_in[9];
    const float* W3 = (const float*)d_in[10];  const float* b3 = (const float*)d_in[11];
    const float* g1 = (const float*)d_in[12];  const float* be1 = (const float*)d_in[13];
    const float* g2 = (const float*)d_in[14];  const float* be2 = (const float*)d_in[15];
    const float* g4 = (const float*)d_in[16];  const float* be4 = (const float*)d_in[17];
    const float* g3 = (const float*)d_in[18];  const float* be3 = (const float*)d_in[19];
    const float* Wl = (const float*)d_in[20];  const float* bl = (const float*)d_in[21];
    float* out = (float*)d_out;

    // setup: degrees + CSR by dst
    zero_main<<<(NN + 255) / 256, 256>>>();
    count_deg<<<(EE + 255) / 256, 256>>>(edst);
    make_dinv<<<(NN + 255) / 256, 256>>>();
    scan_bsum<<<NB, 256>>>();
    scan_tops<<<1, 32>>>();
    scan_final<<<NB, 256>>>();
    fill_csr<<<(EE + 255) / 256, 256>>>(esrc, edst);

    // layer 1: x(64) -> 64
    gemm_k<64><<<(NN + 63) / 64, 256>>>(x, W1);
    gather_k<64><<<(NN * 32 + 255) / 256, 256>>>(b1);
    bn_stats<64><<<256, 256>>>();
    bn_apply<64><<<(NN * 64 + 255) / 256, 256>>>(g1, be1);

    // layer 2: 64 -> 64
    gemm_k<64><<<(NN + 63) / 64, 256>>>(nullptr, W2);
    gather_k<64><<<(NN * 32 + 255) / 256, 256>>>(b2);
    bn_stats<64><<<256, 256>>>();
    bn_apply<64><<<(NN * 64 + 255) / 256, 256>>>(g2, be2);

    // layer 3 (conv4): 64 -> 64
    gemm_k<64><<<(NN + 63) / 64, 256>>>(nullptr, W4);
    gather_k<64><<<(NN * 32 + 255) / 256, 256>>>(b4);
    bn_stats<64><<<256, 256>>>();
    bn_apply<64><<<(NN * 64 + 255) / 256, 256>>>(g4, be4);

    // layer 4 (conv3): 64 -> 32
    gemm_k<32><<<(NN + 127) / 128, 256>>>(nullptr, W3);
    gather_k<32><<<(NN * 32 + 255) / 256, 256>>>(b3);
    bn_stats<32><<<256, 256>>>();
    bn_apply<32><<<(NN * 32 + 255) / 256, 256>>>(g3, be3);

    // pool + classifier
    pool_add<<<(NN * 8 + 255) / 256, 256>>>(batch);
    classify<<<1, 256>>>(Wl, bl, out);
}